// round 1
// baseline (speedup 1.0000x reference)
#include <cuda_runtime.h>
#include <math_constants.h>

namespace {

constexpr int SQ  = 2048;
constexpr int H   = 16;
constexpr int D   = 64;
constexpr int HID = H * D;       // 1024
constexpr int BM  = 64;          // q rows per block
constexpr int BN  = 64;          // kv rows per tile
constexpr int NQT = SQ / BM;     // 32
constexpr int STRIDE = 68;       // padded smem row stride (floats)
constexpr int SMEM_BYTES = 3 * D * STRIDE * (int)sizeof(float);  // 52224

__global__ __launch_bounds__(256)
void fa_fwd(const float* __restrict__ Q, const float* __restrict__ K,
            const float* __restrict__ V, float* __restrict__ Out) {
  // Heavy tiles (large qt) first for causal load balance.
  const int qt  = (NQT - 1) - (int)blockIdx.x;
  const int h   = blockIdx.y;
  const int tid = threadIdx.x;
  const int tx  = tid & 15;   // key / d-col group (4 cols each)
  const int ty  = tid >> 4;   // row group (4 rows each)
  const int q0  = qt * BM;

  extern __shared__ float sm[];
  float* QsT = sm;                  // [D][STRIDE], transposed: QsT[d][r]
  float* KsT = sm + D * STRIDE;     // [D][STRIDE], transposed; reused as PsT[k][r]
  float* Vs  = sm + 2 * D * STRIDE; // [BN][STRIDE], row-major: Vs[k][c]

  constexpr float QSCALE = 0.125f * 1.44269504088896340736f;  // (1/sqrt(64)) * log2(e)

  // ---- Load Q tile transposed + pre-scaled (once per block) ----
  {
    const float* qbase = Q + (size_t)q0 * HID + h * D;
#pragma unroll
    for (int it = 0; it < 4; ++it) {
      int u = tid + 256 * it;
      int r = u >> 4;
      int c = (u & 15) << 2;
      float4 q4 = *reinterpret_cast<const float4*>(qbase + (size_t)r * HID + c);
      QsT[(c + 0) * STRIDE + r] = q4.x * QSCALE;
      QsT[(c + 1) * STRIDE + r] = q4.y * QSCALE;
      QsT[(c + 2) * STRIDE + r] = q4.z * QSCALE;
      QsT[(c + 3) * STRIDE + r] = q4.w * QSCALE;
    }
  }

  float o[4][4];
  float m[4], l[4];
#pragma unroll
  for (int i = 0; i < 4; ++i) {
    m[i] = -CUDART_INF_F;
    l[i] = 0.f;
#pragma unroll
    for (int j = 0; j < 4; ++j) o[i][j] = 0.f;
  }

  for (int kt = 0; kt <= qt; ++kt) {
    __syncthreads();  // prev iter's PsT / Vs reads done (and Q ready on iter 0)

    // ---- Load K (transposed) and V (row-major) tiles ----
    {
      const float* kbase = K + (size_t)kt * BN * HID + h * D;
      const float* vbase = V + (size_t)kt * BN * HID + h * D;
#pragma unroll
      for (int it = 0; it < 4; ++it) {
        int u = tid + 256 * it;
        int r = u >> 4;
        int c = (u & 15) << 2;
        float4 k4 = *reinterpret_cast<const float4*>(kbase + (size_t)r * HID + c);
        KsT[(c + 0) * STRIDE + r] = k4.x;
        KsT[(c + 1) * STRIDE + r] = k4.y;
        KsT[(c + 2) * STRIDE + r] = k4.z;
        KsT[(c + 3) * STRIDE + r] = k4.w;
        float4 v4 = *reinterpret_cast<const float4*>(vbase + (size_t)r * HID + c);
        *reinterpret_cast<float4*>(&Vs[r * STRIDE + c]) = v4;
      }
    }
    __syncthreads();

    // ---- S = Q * K^T (scaled, log2 domain); 4x4 register tile per thread ----
    float s[4][4];
#pragma unroll
    for (int i = 0; i < 4; ++i)
#pragma unroll
      for (int j = 0; j < 4; ++j) s[i][j] = 0.f;

#pragma unroll 8
    for (int d = 0; d < D; ++d) {
      float4 q4 = *reinterpret_cast<const float4*>(&QsT[d * STRIDE + 4 * ty]);
      float4 k4 = *reinterpret_cast<const float4*>(&KsT[d * STRIDE + 4 * tx]);
      float qa[4] = {q4.x, q4.y, q4.z, q4.w};
      float ka[4] = {k4.x, k4.y, k4.z, k4.w};
#pragma unroll
      for (int i = 0; i < 4; ++i)
#pragma unroll
        for (int j = 0; j < 4; ++j) s[i][j] = fmaf(qa[i], ka[j], s[i][j]);
    }
    __syncthreads();  // everyone done reading KsT; it becomes PsT below

    // ---- Causal mask on diagonal tile (q0 == kt*BN there, so compare local idx) ----
    if (kt == qt) {
#pragma unroll
      for (int i = 0; i < 4; ++i)
#pragma unroll
        for (int j = 0; j < 4; ++j)
          if (4 * tx + j > 4 * ty + i) s[i][j] = -CUDART_INF_F;
    }

    // ---- Online softmax (log2 domain). Rows live in 16-lane groups. ----
    float mt[4], rs[4], alpha[4];
#pragma unroll
    for (int i = 0; i < 4; ++i)
      mt[i] = fmaxf(fmaxf(s[i][0], s[i][1]), fmaxf(s[i][2], s[i][3]));
#pragma unroll
    for (int off = 1; off < 16; off <<= 1)
#pragma unroll
      for (int i = 0; i < 4; ++i)
        mt[i] = fmaxf(mt[i], __shfl_xor_sync(0xffffffffu, mt[i], off));

#pragma unroll
    for (int i = 0; i < 4; ++i) {
      float mn = fmaxf(m[i], mt[i]);
      alpha[i] = exp2f(m[i] - mn);  // first tile: exp2(-inf) = 0
      m[i] = mn;
    }
#pragma unroll
    for (int i = 0; i < 4; ++i) {
#pragma unroll
      for (int j = 0; j < 4; ++j) s[i][j] = exp2f(s[i][j] - m[i]);
      rs[i] = (s[i][0] + s[i][1]) + (s[i][2] + s[i][3]);
    }
#pragma unroll
    for (int off = 1; off < 16; off <<= 1)
#pragma unroll
      for (int i = 0; i < 4; ++i)
        rs[i] += __shfl_xor_sync(0xffffffffu, rs[i], off);
#pragma unroll
    for (int i = 0; i < 4; ++i) {
      l[i] = l[i] * alpha[i] + rs[i];
#pragma unroll
      for (int j = 0; j < 4; ++j) o[i][j] *= alpha[i];
    }

    // ---- Store P transposed into the K buffer: PsT[k][r] ----
    float* PsT = KsT;
#pragma unroll
    for (int j = 0; j < 4; ++j) {
      float4 pj = make_float4(s[0][j], s[1][j], s[2][j], s[3][j]);
      *reinterpret_cast<float4*>(&PsT[(4 * tx + j) * STRIDE + 4 * ty]) = pj;
    }
    __syncthreads();

    // ---- O += P * V ----
#pragma unroll 8
    for (int k = 0; k < BN; ++k) {
      float4 p4 = *reinterpret_cast<const float4*>(&PsT[k * STRIDE + 4 * ty]);
      float4 v4 = *reinterpret_cast<const float4*>(&Vs[k * STRIDE + 4 * tx]);
      float pa[4] = {p4.x, p4.y, p4.z, p4.w};
      float va[4] = {v4.x, v4.y, v4.z, v4.w};
#pragma unroll
      for (int i = 0; i < 4; ++i)
#pragma unroll
        for (int j = 0; j < 4; ++j) o[i][j] = fmaf(pa[i], va[j], o[i][j]);
    }
  }

  // ---- Epilogue: normalize and store ----
  float* obase = Out + (size_t)q0 * HID + h * D;
#pragma unroll
  for (int i = 0; i < 4; ++i) {
    float inv = 1.f / l[i];
    float4 o4 = make_float4(o[i][0] * inv, o[i][1] * inv, o[i][2] * inv, o[i][3] * inv);
    *reinterpret_cast<float4*>(obase + (size_t)(4 * ty + i) * HID + 4 * tx) = o4;
  }
}

}  // namespace

extern "C" void kernel_launch(void* const* d_in, const int* in_sizes, int n_in,
                              void* d_out, int out_size) {
  const float* Q = (const float*)d_in[0];
  const float* K = (const float*)d_in[1];
  const float* V = (const float*)d_in[2];
  float* Out = (float*)d_out;

  // 52224 B dynamic smem > 48KB static limit; attribute set is host-side,
  // idempotent, and not a captured stream op.
  cudaFuncSetAttribute(fa_fwd, cudaFuncAttributeMaxDynamicSharedMemorySize, SMEM_BYTES);

  dim3 grid(NQT, H);
  fa_fwd<<<grid, 256, SMEM_BYTES>>>(Q, K, V, Out);
}